// round 13
// baseline (speedup 1.0000x reference)
#include <cuda_runtime.h>
#include <cuda_bf16.h>
#include <math.h>
#include <stdint.h>

#define N_NODES 50000
#define N_EDGES 800000
#define HID     96
#define BM      128
#define KST     104        // bf16 elems per row; 208B stride -> LDSM conflict-free
#define SEG_E   64         // edges per warp-segment in aggregate

// smem byte offsets
#define SM_AHI  0
#define SM_ALO  26624      // 128*104*2
#define SM_BHI  53248
#define SM_BLO  73216      // SM_BHI + 96*104*2
#define SM_BIAS 93184      // b1 (96 floats)
#define SM_BIAS2 93568     // b2 (96 floats)
#define SM_TOT  93952

#define WTILE_BYTES 19968            // 96*104*2
#define WMAT_BYTES  (2 * WTILE_BYTES)

// Scratch (device globals; no allocation allowed)
__device__ float g_h[N_NODES * HID];
__device__ float g_aggr[N_NODES * HID];   // gemm_pre seeds with x_feat; aggregate adds -> x
__device__ unsigned char g_wcvt[3 * WMAT_BYTES];
__device__ int  g_hist[N_NODES + 1];
__device__ int  g_cursor[N_NODES];
__device__ int4 g_sedge[N_EDGES];         // (eid, src, dst, 0) sorted by dst

__device__ __forceinline__ float gelu_exact(float x) {
    return 0.5f * x * (1.0f + erff(x * 0.7071067811865476f));
}
__device__ __forceinline__ void bf16_split(float v, uint16_t& hi, uint16_t& lo) {
    __nv_bfloat16 h = __float2bfloat16(v);
    __nv_bfloat16 l = __float2bfloat16(v - __bfloat162float(h));
    hi = __bfloat16_as_ushort(h);
    lo = __bfloat16_as_ushort(l);
}
__device__ __forceinline__ uint32_t pack_bf16x2(float a_upper, float b_lower) {
    uint32_t d;
    asm("cvt.rn.bf16x2.f32 %0, %1, %2;" : "=r"(d) : "f"(a_upper), "f"(b_lower));
    return d;
}
__device__ __forceinline__ uint32_t smem_u32(const void* p) {
    uint32_t a;
    asm("{ .reg .u64 t; cvta.to.shared.u64 t, %1; cvt.u32.u64 %0, t; }" : "=r"(a) : "l"(p));
    return a;
}
__device__ __forceinline__ void ldsm4(uint32_t& r0, uint32_t& r1, uint32_t& r2, uint32_t& r3,
                                      uint32_t addr) {
    asm volatile("ldmatrix.sync.aligned.m8n8.x4.shared.b16 {%0,%1,%2,%3}, [%4];"
                 : "=r"(r0), "=r"(r1), "=r"(r2), "=r"(r3) : "r"(addr));
}
#define MMA_BF16(acc, a0, a1, a2, a3, b0, b1)                                    \
    asm volatile(                                                                \
        "mma.sync.aligned.m16n8k16.row.col.f32.bf16.bf16.f32 "                   \
        "{%0,%1,%2,%3}, {%4,%5,%6,%7}, {%8,%9}, {%0,%1,%2,%3};"                  \
        : "+f"((acc)[0]), "+f"((acc)[1]), "+f"((acc)[2]), "+f"((acc)[3])         \
        : "r"(a0), "r"(a1), "r"(a2), "r"(a3), "r"(b0), "r"(b1))

#define CP16(dst_u32, src_ptr)                                                   \
    asm volatile("cp.async.cg.shared.global [%0], [%1], 16;"                     \
                 :: "r"(dst_u32), "l"(src_ptr) : "memory")

// One-time W convert (also zeroes g_hist for the histogram that follows).
__global__ void wconv_kernel(const float* __restrict__ W0, const float* __restrict__ W1,
                             const float* __restrict__ W2) {
    // zero g_hist (grid-stride over all 96*256 threads)
    for (int i = blockIdx.x * blockDim.x + threadIdx.x; i <= N_NODES;
         i += gridDim.x * blockDim.x)
        g_hist[i] = 0;
    const int m = blockIdx.x >> 5, s = blockIdx.x & 31;
    const float* W = (m == 0) ? W0 : (m == 1) ? W1 : W2;
    uint16_t* dhi = (uint16_t*)(g_wcvt + m * WMAT_BYTES);
    uint16_t* dlo = (uint16_t*)(g_wcvt + m * WMAT_BYTES + WTILE_BYTES);
    const int e0 = s * 288, e1 = e0 + 288;
    for (int e = e0 + threadIdx.x; e < e1; e += blockDim.x) {
        int k = e / HID, n = e - (e / HID) * HID;
        uint16_t hi, lo;
        bf16_split(W[e], hi, lo);
        dhi[n * KST + k] = hi;
        dlo[n * KST + k] = lo;
    }
}

__global__ void hist_kernel(const int* __restrict__ dst) {
    int e = blockIdx.x * 256 + threadIdx.x;
    if (e < N_EDGES) atomicAdd(&g_hist[dst[e] + 1], 1);
}
#define SCAN_T 1024
#define SCAN_CHUNK 49          // 1024*49 = 50176 >= N_NODES+1
__global__ void scan_kernel() {
    __shared__ int part[SCAN_T];
    const int t = threadIdx.x;
    const int base = t * SCAN_CHUNK;
    int s = 0;
    for (int i = 0; i < SCAN_CHUNK; i++) {
        int idx = base + i;
        if (idx <= N_NODES) s += g_hist[idx];
    }
    part[t] = s;
    __syncthreads();
    for (int off = 1; off < SCAN_T; off <<= 1) {
        int v = (t >= off) ? part[t - off] : 0;
        __syncthreads();
        part[t] += v;
        __syncthreads();
    }
    int run = (t == 0) ? 0 : part[t - 1];
    for (int i = 0; i < SCAN_CHUNK; i++) {
        int idx = base + i;
        if (idx <= N_NODES) {
            run += g_hist[idx];
            g_hist[idx] = run;                     // H[d] = start offset of dst d
            if (idx < N_NODES) g_cursor[idx] = run; // cursor fused here
        }
    }
}
__global__ void scatter_kernel(const int* __restrict__ src, const int* __restrict__ dst) {
    int e = blockIdx.x * 256 + threadIdx.x;
    if (e < N_EDGES) {
        int d = dst[e];
        int p = atomicAdd(&g_cursor[d], 1);
        g_sedge[p] = make_int4(e, src[e], d, 0);
    }
}

// Sorted segmented reduce: warp handles SEG_E consecutive dst-sorted edges.
// Lanes 0-23 own one float4 column. Flush (rare, warp-uniform) on dst change.
__global__ __launch_bounds__(256)
void aggregate_kernel(const float* __restrict__ bases) {
    const int wg = (blockIdx.x * 256 + threadIdx.x) >> 5;
    const int l  = threadIdx.x & 31;
    const int nseg = N_EDGES / SEG_E;                 // 12500 exact
    if (wg >= nseg) return;
    const int e0 = wg * SEG_E, e1 = e0 + SEG_E;
    const bool act = (l < 24);
    const float4* b4 = (const float4*)bases;
    const float4* h4 = (const float4*)g_h;
    float4 acc = make_float4(0.f, 0.f, 0.f, 0.f);
    int cur = g_sedge[e0].z;
#pragma unroll 4
    for (int e = e0; e < e1; e++) {
        int4 es = g_sedge[e];                          // uniform, L1-resident line
        if (es.z != cur) {                             // warp-uniform branch
            if (act) {
                float* p = g_aggr + (size_t)cur * HID + l * 4;
                asm volatile("red.global.add.v4.f32 [%0], {%1, %2, %3, %4};"
                             :: "l"(p), "f"(acc.x), "f"(acc.y), "f"(acc.z), "f"(acc.w)
                             : "memory");
            }
            acc = make_float4(0.f, 0.f, 0.f, 0.f);
            cur = es.z;
        }
        if (act) {
            float4 b = b4[(size_t)es.x * 24 + l];
            float4 h = h4[(size_t)es.y * 24 + l];
            acc.x = fmaf(b.x, h.x, acc.x);
            acc.y = fmaf(b.y, h.y, acc.y);
            acc.z = fmaf(b.z, h.z, acc.z);
            acc.w = fmaf(b.w, h.w, acc.w);
        }
    }
    if (act) {
        float* p = g_aggr + (size_t)cur * HID + l * 4;
        asm volatile("red.global.add.v4.f32 [%0], {%1, %2, %3, %4};"
                     :: "l"(p), "f"(acc.x), "f"(acc.y), "f"(acc.z), "f"(acc.w)
                     : "memory");
    }
}

// Shared MMA helper
struct FragOffs { uint32_t aoff[2]; uint32_t boff[3]; };
__device__ __forceinline__ void mma_pass(const uint32_t sbase, const FragOffs& fo,
                                         float acc[2][6][4]) {
#pragma unroll
    for (int ks = 0; ks < 6; ks++) {
        const uint32_t k0 = ks * 16;
        uint32_t aH[2][4], aL[2][4], bH[6][2], bL[6][2];
#pragma unroll
        for (int mt = 0; mt < 2; mt++) {
            ldsm4(aH[mt][0], aH[mt][1], aH[mt][2], aH[mt][3],
                  sbase + SM_AHI + 2 * (fo.aoff[mt] + k0));
            ldsm4(aL[mt][0], aL[mt][1], aL[mt][2], aL[mt][3],
                  sbase + SM_ALO + 2 * (fo.aoff[mt] + k0));
        }
#pragma unroll
        for (int p = 0; p < 3; p++) {
            ldsm4(bH[2 * p][0], bH[2 * p][1], bH[2 * p + 1][0], bH[2 * p + 1][1],
                  sbase + SM_BHI + 2 * (fo.boff[p] + k0));
            ldsm4(bL[2 * p][0], bL[2 * p][1], bL[2 * p + 1][0], bL[2 * p + 1][1],
                  sbase + SM_BLO + 2 * (fo.boff[p] + k0));
        }
#pragma unroll
        for (int mt = 0; mt < 2; mt++)
#pragma unroll
            for (int nt = 0; nt < 6; nt++)
                MMA_BF16(acc[mt][nt], aH[mt][0], aH[mt][1], aH[mt][2], aH[mt][3],
                         bH[nt][0], bH[nt][1]);
#pragma unroll
        for (int mt = 0; mt < 2; mt++)
#pragma unroll
            for (int nt = 0; nt < 6; nt++)
                MMA_BF16(acc[mt][nt], aH[mt][0], aH[mt][1], aH[mt][2], aH[mt][3],
                         bL[nt][0], bL[nt][1]);
#pragma unroll
        for (int mt = 0; mt < 2; mt++)
#pragma unroll
            for (int nt = 0; nt < 6; nt++)
                MMA_BF16(acc[mt][nt], aL[mt][0], aL[mt][1], aL[mt][2], aL[mt][3],
                         bH[nt][0], bH[nt][1]);
    }
}

// PRE: h = gelu(x_feat @ W_pre + b_pre); seed g_aggr = x_feat
__global__ __launch_bounds__(256, 2)
void gemm_pre(const float* __restrict__ A0,
              const unsigned char* __restrict__ wcvt,
              const float* __restrict__ bias,
              float* __restrict__ out) {
    extern __shared__ char smem[];
    uint16_t* Ahi = (uint16_t*)(smem + SM_AHI);
    uint16_t* Alo = (uint16_t*)(smem + SM_ALO);
    float*    Bsm = (float*)(smem + SM_BIAS);

    const int tid  = threadIdx.x;
    const int row0 = blockIdx.x * BM;
    const uint32_t sbase = smem_u32(smem);

    {
        const char* src = (const char*)wcvt;
#pragma unroll
        for (int i = 0; i < 10; i++) {
            int idx = tid + 256 * i;
            if (idx < WMAT_BYTES / 16) CP16(sbase + SM_BHI + 16 * idx, src + 16 * idx);
        }
        asm volatile("cp.async.commit_group;" ::: "memory");
    }
    if (tid < 24) ((float4*)Bsm)[tid] = ((const float4*)bias)[tid];

#pragma unroll
    for (int i = 0; i < 12; i++) {
        int idx4 = tid + 256 * i;
        int r = idx4 / 24, c4 = idx4 - (idx4 / 24) * 24;
        int row = row0 + r;
        float4 v = make_float4(0.f, 0.f, 0.f, 0.f);
        if (row < N_NODES) {
            v = ((const float4*)(A0 + (size_t)row * HID))[c4];
            ((float4*)(g_aggr + (size_t)row * HID))[c4] = v;   // seed aggr with x_feat
        }
        uint32_t h01 = pack_bf16x2(v.y, v.x);
        uint32_t h23 = pack_bf16x2(v.w, v.z);
        float hx = __uint_as_float(h01 << 16);
        float hy = __uint_as_float(h01 & 0xffff0000u);
        float hz = __uint_as_float(h23 << 16);
        float hw = __uint_as_float(h23 & 0xffff0000u);
        uint32_t l01 = pack_bf16x2(v.y - hy, v.x - hx);
        uint32_t l23 = pack_bf16x2(v.w - hw, v.z - hz);
        int eo = r * KST + c4 * 4;
        *(uint2*)(Ahi + eo) = make_uint2(h01, h23);
        *(uint2*)(Alo + eo) = make_uint2(l01, l23);
    }
    asm volatile("cp.async.wait_group 0;" ::: "memory");
    __syncthreads();

    const int w  = tid >> 5;
    const int l  = tid & 31;
    const int m0 = (w & 3) * 32;
    const int n0 = (w >> 2) * 48;
    FragOffs fo;
#pragma unroll
    for (int mt = 0; mt < 2; mt++)
        fo.aoff[mt] = (uint32_t)((m0 + mt * 16 + (l & 15)) * KST + (l >> 4) * 8);
#pragma unroll
    for (int p = 0; p < 3; p++)
        fo.boff[p] = (uint32_t)((n0 + p * 16 + (l >> 4) * 8 + (l & 7)) * KST + ((l >> 3) & 1) * 8);

    float acc[2][6][4];
#pragma unroll
    for (int mt = 0; mt < 2; mt++)
#pragma unroll
        for (int nt = 0; nt < 6; nt++)
#pragma unroll
            for (int q = 0; q < 4; q++) acc[mt][nt][q] = 0.f;

    mma_pass(sbase, fo, acc);

    const int lr = l >> 2;
    const int lk = 2 * (l & 3);
#pragma unroll
    for (int mt = 0; mt < 2; mt++) {
#pragma unroll
        for (int nt = 0; nt < 6; nt++) {
            int col = n0 + nt * 8 + lk;
            float bx = Bsm[col], by = Bsm[col + 1];
            int r1 = row0 + m0 + mt * 16 + lr;
            int r2 = r1 + 8;
            if (r1 < N_NODES) {
                size_t o = (size_t)r1 * HID + col;
                *(float2*)(out + o) = make_float2(gelu_exact(acc[mt][nt][0] + bx),
                                                  gelu_exact(acc[mt][nt][1] + by));
            }
            if (r2 < N_NODES) {
                size_t o = (size_t)r2 * HID + col;
                *(float2*)(out + o) = make_float2(gelu_exact(acc[mt][nt][2] + bx),
                                                  gelu_exact(acc[mt][nt][3] + by));
            }
        }
    }
}

// FFN fused: t = gelu(x@W1+b1) in-tile, then out = x + gelu(t@W2+b2)
__global__ __launch_bounds__(256, 2)
void gemm_ffn(const unsigned char* __restrict__ w1cvt,
              const unsigned char* __restrict__ w2cvt,
              const float* __restrict__ b1,
              const float* __restrict__ b2,
              float* __restrict__ out) {
    extern __shared__ char smem[];
    uint16_t* Ahi = (uint16_t*)(smem + SM_AHI);
    uint16_t* Alo = (uint16_t*)(smem + SM_ALO);
    float*    B1s = (float*)(smem + SM_BIAS);
    float*    B2s = (float*)(smem + SM_BIAS2);

    const int tid  = threadIdx.x;
    const int row0 = blockIdx.x * BM;
    const uint32_t sbase = smem_u32(smem);

    {
        const char* src = (const char*)w1cvt;
#pragma unroll
        for (int i = 0; i < 10; i++) {
            int idx = tid + 256 * i;
            if (idx < WMAT_BYTES / 16) CP16(sbase + SM_BHI + 16 * idx, src + 16 * idx);
        }
        asm volatile("cp.async.commit_group;" ::: "memory");
    }
    if (tid < 24) {
        ((float4*)B1s)[tid] = ((const float4*)b1)[tid];
        ((float4*)B2s)[tid] = ((const float4*)b2)[tid];
    }

#pragma unroll
    for (int i = 0; i < 12; i++) {
        int idx4 = tid + 256 * i;
        int r = idx4 / 24, c4 = idx4 - (idx4 / 24) * 24;
        int row = row0 + r;
        float4 v = make_float4(0.f, 0.f, 0.f, 0.f);
        if (row < N_NODES)
            v = ((const float4*)(g_aggr + (size_t)row * HID))[c4];
        uint32_t h01 = pack_bf16x2(v.y, v.x);
        uint32_t h23 = pack_bf16x2(v.w, v.z);
        float hx = __uint_as_float(h01 << 16);
        float hy = __uint_as_float(h01 & 0xffff0000u);
        float hz = __uint_as_float(h23 << 16);
        float hw = __uint_as_float(h23 & 0xffff0000u);
        uint32_t l01 = pack_bf16x2(v.y - hy, v.x - hx);
        uint32_t l23 = pack_bf16x2(v.w - hw, v.z - hz);
        int eo = r * KST + c4 * 4;
        *(uint2*)(Ahi + eo) = make_uint2(h01, h23);
        *(uint2*)(Alo + eo) = make_uint2(l01, l23);
    }
    asm volatile("cp.async.wait_group 0;" ::: "memory");
    __syncthreads();

    const int w  = tid >> 5;
    const int l  = tid & 31;
    const int m0 = (w & 3) * 32;
    const int n0 = (w >> 2) * 48;
    FragOffs fo;
#pragma unroll
    for (int mt = 0; mt < 2; mt++)
        fo.aoff[mt] = (uint32_t)((m0 + mt * 16 + (l & 15)) * KST + (l >> 4) * 8);
#pragma unroll
    for (int p = 0; p < 3; p++)
        fo.boff[p] = (uint32_t)((n0 + p * 16 + (l >> 4) * 8 + (l & 7)) * KST + ((l >> 3) & 1) * 8);

    float acc[2][6][4];
#pragma unroll
    for (int mt = 0; mt < 2; mt++)
#pragma unroll
        for (int nt = 0; nt < 6; nt++)
#pragma unroll
            for (int q = 0; q < 4; q++) acc[mt][nt][q] = 0.f;

    mma_pass(sbase, fo, acc);      // U = x @ W1

    __syncthreads();

    {
        const char* src = (const char*)w2cvt;
#pragma unroll
        for (int i = 0; i < 10; i++) {
            int idx = tid + 256 * i;
            if (idx < WMAT_BYTES / 16) CP16(sbase + SM_BHI + 16 * idx, src + 16 * idx);
        }
        asm volatile("cp.async.commit_group;" ::: "memory");
    }

    const int lr = l >> 2;
    const int lk = 2 * (l & 3);
#pragma unroll
    for (int mt = 0; mt < 2; mt++) {
#pragma unroll
        for (int nt = 0; nt < 6; nt++) {
            int col = n0 + nt * 8 + lk;
            float bx = B1s[col], by = B1s[col + 1];
            int r1 = m0 + mt * 16 + lr;
            int r2 = r1 + 8;
            float t0 = gelu_exact(acc[mt][nt][0] + bx);
            float t1 = gelu_exact(acc[mt][nt][1] + by);
            float t2 = gelu_exact(acc[mt][nt][2] + bx);
            float t3 = gelu_exact(acc[mt][nt][3] + by);
            uint32_t hA = pack_bf16x2(t1, t0);
            uint32_t hB = pack_bf16x2(t3, t2);
            float hA0 = __uint_as_float(hA << 16);
            float hA1 = __uint_as_float(hA & 0xffff0000u);
            float hB0 = __uint_as_float(hB << 16);
            float hB1 = __uint_as_float(hB & 0xffff0000u);
            uint32_t lA = pack_bf16x2(t1 - hA1, t0 - hA0);
            uint32_t lB = pack_bf16x2(t3 - hB1, t2 - hB0);
            *(uint32_t*)&Ahi[r1 * KST + col] = hA;
            *(uint32_t*)&Alo[r1 * KST + col] = lA;
            *(uint32_t*)&Ahi[r2 * KST + col] = hB;
            *(uint32_t*)&Alo[r2 * KST + col] = lB;
        }
    }
    asm volatile("cp.async.wait_group 0;" ::: "memory");
    __syncthreads();

#pragma unroll
    for (int mt = 0; mt < 2; mt++)
#pragma unroll
        for (int nt = 0; nt < 6; nt++)
#pragma unroll
            for (int q = 0; q < 4; q++) acc[mt][nt][q] = 0.f;

    mma_pass(sbase, fo, acc);      // V = t @ W2

#pragma unroll
    for (int mt = 0; mt < 2; mt++) {
#pragma unroll
        for (int nt = 0; nt < 6; nt++) {
            int col = n0 + nt * 8 + lk;
            float bx = B2s[col], by = B2s[col + 1];
            int r1 = row0 + m0 + mt * 16 + lr;
            int r2 = r1 + 8;
            if (r1 < N_NODES) {
                size_t o = (size_t)r1 * HID + col;
                float2 xv = *(const float2*)(g_aggr + o);
                *(float2*)(out + o) = make_float2(xv.x + gelu_exact(acc[mt][nt][0] + bx),
                                                  xv.y + gelu_exact(acc[mt][nt][1] + by));
            }
            if (r2 < N_NODES) {
                size_t o = (size_t)r2 * HID + col;
                float2 xv = *(const float2*)(g_aggr + o);
                *(float2*)(out + o) = make_float2(xv.x + gelu_exact(acc[mt][nt][2] + bx),
                                                  xv.y + gelu_exact(acc[mt][nt][3] + by));
            }
        }
    }
}

extern "C" void kernel_launch(void* const* d_in, const int* in_sizes, int n_in,
                              void* d_out, int out_size) {
    const float* x_feat = (const float*)d_in[0];
    const float* bases  = (const float*)d_in[1];
    const float* W_pre  = (const float*)d_in[2];
    const float* b_pre  = (const float*)d_in[3];
    const float* W1     = (const float*)d_in[4];
    const float* b1     = (const float*)d_in[5];
    const float* W2     = (const float*)d_in[6];
    const float* b2     = (const float*)d_in[7];
    const int*   src    = (const int*)d_in[8];
    const int*   dst    = (const int*)d_in[9];
    float* out = (float*)d_out;

    cudaFuncSetAttribute(gemm_pre, cudaFuncAttributeMaxDynamicSharedMemorySize, SM_TOT);
    cudaFuncSetAttribute(gemm_ffn, cudaFuncAttributeMaxDynamicSharedMemorySize, SM_TOT);

    float* g_h_p;    cudaGetSymbolAddress((void**)&g_h_p, g_h);
    unsigned char* wcvt_p; cudaGetSymbolAddress((void**)&wcvt_p, g_wcvt);

    const int gemm_grid = (N_NODES + BM - 1) / BM;   // 391
    const int agg_grid  = (N_EDGES / SEG_E * 32 + 255) / 256;   // 12500 warps

    // W convert + g_hist zero
    wconv_kernel<<<96, 256>>>(W_pre, W1, W2);
    // CSR build (independent of g_h; overlaps conceptually with gemm_pre work)
    hist_kernel<<<(N_EDGES + 255) / 256, 256>>>(dst);
    scan_kernel<<<1, SCAN_T>>>();
    scatter_kernel<<<(N_EDGES + 255) / 256, 256>>>(src, dst);
    // 1) h = gelu(x_feat @ W_pre + b_pre); g_aggr = x_feat
    gemm_pre<<<gemm_grid, 256, SM_TOT>>>(x_feat, wcvt_p, b_pre, g_h_p);
    // 2) g_aggr += segment_sum(bases * h[src]) by dst (sorted, few atomics)
    aggregate_kernel<<<agg_grid, 256>>>(bases);
    // 3+4) t = gelu(x@W1+b1); out = x + gelu(t@W2+b2)
    gemm_ffn<<<gemm_grid, 256, SM_TOT>>>(wcvt_p + WMAT_BYTES, wcvt_p + 2 * WMAT_BYTES,
                                         b1, b2, out);
}

// round 14
// speedup vs baseline: 1.7548x; 1.7548x over previous
#include <cuda_runtime.h>
#include <cuda_bf16.h>
#include <math.h>
#include <stdint.h>

#define N_NODES 50000
#define N_EDGES 800000
#define HID     96
#define BM      128
#define KST     104        // bf16 elems per row; 208B stride -> LDSM conflict-free

// smem byte offsets
#define SM_AHI  0
#define SM_ALO  26624      // 128*104*2
#define SM_BHI  53248
#define SM_BLO  73216      // SM_BHI + 96*104*2
#define SM_BIAS 93184      // b1 (96 floats)
#define SM_BIAS2 93568     // b2 (96 floats)
#define SM_TOT  93952

#define WTILE_BYTES 19968            // 96*104*2
#define WMAT_BYTES  (2 * WTILE_BYTES)

// Scratch (device globals; no allocation allowed)
__device__ float g_h[N_NODES * HID];
__device__ float g_aggr[N_NODES * HID];   // gemm_pre seeds with x_feat; edge adds msgs -> x
__device__ unsigned char g_wcvt[3 * WMAT_BYTES];

// Fast exact-enough GELU: erf via Abramowitz-Stegun 7.1.26 (abs err ~1e-6 in fp32).
// Branchless; uses MUFU.RCP + MUFU.EX2 via fast intrinsics.
__device__ __forceinline__ float gelu_exact(float x) {
    float z  = x * 0.7071067811865476f;
    float az = fabsf(z);
    float t  = __fdividef(1.0f, fmaf(0.3275911f, az, 1.0f));   // MUFU.RCP path
    float p  = fmaf(1.061405429f, t, -1.453152027f);
    p = fmaf(p, t, 1.421413741f);
    p = fmaf(p, t, -0.284496736f);
    p = fmaf(p, t, 0.254829592f);
    p = p * t;
    float e  = __expf(-az * az);                               // MUFU.EX2 path
    float er = fmaf(-p, e, 1.0f);                              // erf(|z|)
    er = copysignf(er, z);
    return 0.5f * x * (1.0f + er);
}
__device__ __forceinline__ void bf16_split(float v, uint16_t& hi, uint16_t& lo) {
    __nv_bfloat16 h = __float2bfloat16(v);
    __nv_bfloat16 l = __float2bfloat16(v - __bfloat162float(h));
    hi = __bfloat16_as_ushort(h);
    lo = __bfloat16_as_ushort(l);
}
__device__ __forceinline__ uint32_t pack_bf16x2(float a_upper, float b_lower) {
    uint32_t d;
    asm("cvt.rn.bf16x2.f32 %0, %1, %2;" : "=r"(d) : "f"(a_upper), "f"(b_lower));
    return d;
}
__device__ __forceinline__ uint32_t smem_u32(const void* p) {
    uint32_t a;
    asm("{ .reg .u64 t; cvta.to.shared.u64 t, %1; cvt.u32.u64 %0, t; }" : "=r"(a) : "l"(p));
    return a;
}
__device__ __forceinline__ void ldsm4(uint32_t& r0, uint32_t& r1, uint32_t& r2, uint32_t& r3,
                                      uint32_t addr) {
    asm volatile("ldmatrix.sync.aligned.m8n8.x4.shared.b16 {%0,%1,%2,%3}, [%4];"
                 : "=r"(r0), "=r"(r1), "=r"(r2), "=r"(r3) : "r"(addr));
}
#define MMA_BF16(acc, a0, a1, a2, a3, b0, b1)                                    \
    asm volatile(                                                                \
        "mma.sync.aligned.m16n8k16.row.col.f32.bf16.bf16.f32 "                   \
        "{%0,%1,%2,%3}, {%4,%5,%6,%7}, {%8,%9}, {%0,%1,%2,%3};"                  \
        : "+f"((acc)[0]), "+f"((acc)[1]), "+f"((acc)[2]), "+f"((acc)[3])         \
        : "r"(a0), "r"(a1), "r"(a2), "r"(a3), "r"(b0), "r"(b1))

#define CP16(dst_u32, src_ptr)                                                   \
    asm volatile("cp.async.cg.shared.global [%0], [%1], 16;"                     \
                 :: "r"(dst_u32), "l"(src_ptr) : "memory")

// One-time W convert, parallel.
__global__ void wconv_kernel(const float* __restrict__ W0, const float* __restrict__ W1,
                             const float* __restrict__ W2) {
    const int m = blockIdx.x >> 5, s = blockIdx.x & 31;
    const float* W = (m == 0) ? W0 : (m == 1) ? W1 : W2;
    uint16_t* dhi = (uint16_t*)(g_wcvt + m * WMAT_BYTES);
    uint16_t* dlo = (uint16_t*)(g_wcvt + m * WMAT_BYTES + WTILE_BYTES);
    const int e0 = s * 288, e1 = e0 + 288;
    for (int e = e0 + threadIdx.x; e < e1; e += blockDim.x) {
        int k = e / HID, n = e - (e / HID) * HID;
        uint16_t hi, lo;
        bf16_split(W[e], hi, lo);
        dhi[n * KST + k] = hi;
        dlo[n * KST + k] = lo;
    }
}

// Shared MMA helper
struct FragOffs { uint32_t aoff[2]; uint32_t boff[3]; };
__device__ __forceinline__ void mma_pass(const uint32_t sbase, const FragOffs& fo,
                                         float acc[2][6][4]) {
#pragma unroll
    for (int ks = 0; ks < 6; ks++) {
        const uint32_t k0 = ks * 16;
        uint32_t aH[2][4], aL[2][4], bH[6][2], bL[6][2];
#pragma unroll
        for (int mt = 0; mt < 2; mt++) {
            ldsm4(aH[mt][0], aH[mt][1], aH[mt][2], aH[mt][3],
                  sbase + SM_AHI + 2 * (fo.aoff[mt] + k0));
            ldsm4(aL[mt][0], aL[mt][1], aL[mt][2], aL[mt][3],
                  sbase + SM_ALO + 2 * (fo.aoff[mt] + k0));
        }
#pragma unroll
        for (int p = 0; p < 3; p++) {
            ldsm4(bH[2 * p][0], bH[2 * p][1], bH[2 * p + 1][0], bH[2 * p + 1][1],
                  sbase + SM_BHI + 2 * (fo.boff[p] + k0));
            ldsm4(bL[2 * p][0], bL[2 * p][1], bL[2 * p + 1][0], bL[2 * p + 1][1],
                  sbase + SM_BLO + 2 * (fo.boff[p] + k0));
        }
#pragma unroll
        for (int mt = 0; mt < 2; mt++)
#pragma unroll
            for (int nt = 0; nt < 6; nt++)
                MMA_BF16(acc[mt][nt], aH[mt][0], aH[mt][1], aH[mt][2], aH[mt][3],
                         bH[nt][0], bH[nt][1]);
#pragma unroll
        for (int mt = 0; mt < 2; mt++)
#pragma unroll
            for (int nt = 0; nt < 6; nt++)
                MMA_BF16(acc[mt][nt], aH[mt][0], aH[mt][1], aH[mt][2], aH[mt][3],
                         bL[nt][0], bL[nt][1]);
#pragma unroll
        for (int mt = 0; mt < 2; mt++)
#pragma unroll
            for (int nt = 0; nt < 6; nt++)
                MMA_BF16(acc[mt][nt], aL[mt][0], aL[mt][1], aL[mt][2], aL[mt][3],
                         bH[nt][0], bH[nt][1]);
    }
}

// PRE: h = gelu(x_feat @ W_pre + b_pre); seed g_aggr = x_feat
__global__ __launch_bounds__(256, 2)
void gemm_pre(const float* __restrict__ A0,
              const unsigned char* __restrict__ wcvt,
              const float* __restrict__ bias,
              float* __restrict__ out) {
    extern __shared__ char smem[];
    uint16_t* Ahi = (uint16_t*)(smem + SM_AHI);
    uint16_t* Alo = (uint16_t*)(smem + SM_ALO);
    float*    Bsm = (float*)(smem + SM_BIAS);

    const int tid  = threadIdx.x;
    const int row0 = blockIdx.x * BM;
    const uint32_t sbase = smem_u32(smem);

    {
        const char* src = (const char*)wcvt;
#pragma unroll
        for (int i = 0; i < 10; i++) {
            int idx = tid + 256 * i;
            if (idx < WMAT_BYTES / 16) CP16(sbase + SM_BHI + 16 * idx, src + 16 * idx);
        }
        asm volatile("cp.async.commit_group;" ::: "memory");
    }
    if (tid < 24) ((float4*)Bsm)[tid] = ((const float4*)bias)[tid];

#pragma unroll
    for (int i = 0; i < 12; i++) {
        int idx4 = tid + 256 * i;
        int r = idx4 / 24, c4 = idx4 - (idx4 / 24) * 24;
        int row = row0 + r;
        float4 v = make_float4(0.f, 0.f, 0.f, 0.f);
        if (row < N_NODES) {
            v = ((const float4*)(A0 + (size_t)row * HID))[c4];
            ((float4*)(g_aggr + (size_t)row * HID))[c4] = v;   // seed aggr with x_feat
        }
        uint32_t h01 = pack_bf16x2(v.y, v.x);
        uint32_t h23 = pack_bf16x2(v.w, v.z);
        float hx = __uint_as_float(h01 << 16);
        float hy = __uint_as_float(h01 & 0xffff0000u);
        float hz = __uint_as_float(h23 << 16);
        float hw = __uint_as_float(h23 & 0xffff0000u);
        uint32_t l01 = pack_bf16x2(v.y - hy, v.x - hx);
        uint32_t l23 = pack_bf16x2(v.w - hw, v.z - hz);
        int eo = r * KST + c4 * 4;
        *(uint2*)(Ahi + eo) = make_uint2(h01, h23);
        *(uint2*)(Alo + eo) = make_uint2(l01, l23);
    }
    asm volatile("cp.async.wait_group 0;" ::: "memory");
    __syncthreads();

    const int w  = tid >> 5;
    const int l  = tid & 31;
    const int m0 = (w & 3) * 32;
    const int n0 = (w >> 2) * 48;
    FragOffs fo;
#pragma unroll
    for (int mt = 0; mt < 2; mt++)
        fo.aoff[mt] = (uint32_t)((m0 + mt * 16 + (l & 15)) * KST + (l >> 4) * 8);
#pragma unroll
    for (int p = 0; p < 3; p++)
        fo.boff[p] = (uint32_t)((n0 + p * 16 + (l >> 4) * 8 + (l & 7)) * KST + ((l >> 3) & 1) * 8);

    float acc[2][6][4];
#pragma unroll
    for (int mt = 0; mt < 2; mt++)
#pragma unroll
        for (int nt = 0; nt < 6; nt++)
#pragma unroll
            for (int q = 0; q < 4; q++) acc[mt][nt][q] = 0.f;

    mma_pass(sbase, fo, acc);

    const int lr = l >> 2;
    const int lk = 2 * (l & 3);
#pragma unroll
    for (int mt = 0; mt < 2; mt++) {
#pragma unroll
        for (int nt = 0; nt < 6; nt++) {
            int col = n0 + nt * 8 + lk;
            float bx = Bsm[col], by = Bsm[col + 1];
            int r1 = row0 + m0 + mt * 16 + lr;
            int r2 = r1 + 8;
            if (r1 < N_NODES) {
                size_t o = (size_t)r1 * HID + col;
                *(float2*)(out + o) = make_float2(gelu_exact(acc[mt][nt][0] + bx),
                                                  gelu_exact(acc[mt][nt][1] + by));
            }
            if (r2 < N_NODES) {
                size_t o = (size_t)r2 * HID + col;
                *(float2*)(out + o) = make_float2(gelu_exact(acc[mt][nt][2] + bx),
                                                  gelu_exact(acc[mt][nt][3] + by));
            }
        }
    }
}

// FFN fused: t = gelu(x@W1+b1) in-tile, then out = x + gelu(t@W2+b2)
__global__ __launch_bounds__(256, 2)
void gemm_ffn(const unsigned char* __restrict__ w1cvt,
              const unsigned char* __restrict__ w2cvt,
              const float* __restrict__ b1,
              const float* __restrict__ b2,
              float* __restrict__ out) {
    extern __shared__ char smem[];
    uint16_t* Ahi = (uint16_t*)(smem + SM_AHI);
    uint16_t* Alo = (uint16_t*)(smem + SM_ALO);
    float*    B1s = (float*)(smem + SM_BIAS);
    float*    B2s = (float*)(smem + SM_BIAS2);

    const int tid  = threadIdx.x;
    const int row0 = blockIdx.x * BM;
    const uint32_t sbase = smem_u32(smem);

    {
        const char* src = (const char*)w1cvt;
#pragma unroll
        for (int i = 0; i < 10; i++) {
            int idx = tid + 256 * i;
            if (idx < WMAT_BYTES / 16) CP16(sbase + SM_BHI + 16 * idx, src + 16 * idx);
        }
        asm volatile("cp.async.commit_group;" ::: "memory");
    }
    if (tid < 24) {
        ((float4*)B1s)[tid] = ((const float4*)b1)[tid];
        ((float4*)B2s)[tid] = ((const float4*)b2)[tid];
    }

#pragma unroll
    for (int i = 0; i < 12; i++) {
        int idx4 = tid + 256 * i;
        int r = idx4 / 24, c4 = idx4 - (idx4 / 24) * 24;
        int row = row0 + r;
        float4 v = make_float4(0.f, 0.f, 0.f, 0.f);
        if (row < N_NODES)
            v = ((const float4*)(g_aggr + (size_t)row * HID))[c4];
        uint32_t h01 = pack_bf16x2(v.y, v.x);
        uint32_t h23 = pack_bf16x2(v.w, v.z);
        float hx = __uint_as_float(h01 << 16);
        float hy = __uint_as_float(h01 & 0xffff0000u);
        float hz = __uint_as_float(h23 << 16);
        float hw = __uint_as_float(h23 & 0xffff0000u);
        uint32_t l01 = pack_bf16x2(v.y - hy, v.x - hx);
        uint32_t l23 = pack_bf16x2(v.w - hw, v.z - hz);
        int eo = r * KST + c4 * 4;
        *(uint2*)(Ahi + eo) = make_uint2(h01, h23);
        *(uint2*)(Alo + eo) = make_uint2(l01, l23);
    }
    asm volatile("cp.async.wait_group 0;" ::: "memory");
    __syncthreads();

    const int w  = tid >> 5;
    const int l  = tid & 31;
    const int m0 = (w & 3) * 32;
    const int n0 = (w >> 2) * 48;
    FragOffs fo;
#pragma unroll
    for (int mt = 0; mt < 2; mt++)
        fo.aoff[mt] = (uint32_t)((m0 + mt * 16 + (l & 15)) * KST + (l >> 4) * 8);
#pragma unroll
    for (int p = 0; p < 3; p++)
        fo.boff[p] = (uint32_t)((n0 + p * 16 + (l >> 4) * 8 + (l & 7)) * KST + ((l >> 3) & 1) * 8);

    float acc[2][6][4];
#pragma unroll
    for (int mt = 0; mt < 2; mt++)
#pragma unroll
        for (int nt = 0; nt < 6; nt++)
#pragma unroll
            for (int q = 0; q < 4; q++) acc[mt][nt][q] = 0.f;

    mma_pass(sbase, fo, acc);      // U = x @ W1

    __syncthreads();

    {
        const char* src = (const char*)w2cvt;
#pragma unroll
        for (int i = 0; i < 10; i++) {
            int idx = tid + 256 * i;
            if (idx < WMAT_BYTES / 16) CP16(sbase + SM_BHI + 16 * idx, src + 16 * idx);
        }
        asm volatile("cp.async.commit_group;" ::: "memory");
    }

    const int lr = l >> 2;
    const int lk = 2 * (l & 3);
#pragma unroll
    for (int mt = 0; mt < 2; mt++) {
#pragma unroll
        for (int nt = 0; nt < 6; nt++) {
            int col = n0 + nt * 8 + lk;
            float bx = B1s[col], by = B1s[col + 1];
            int r1 = m0 + mt * 16 + lr;
            int r2 = r1 + 8;
            float t0 = gelu_exact(acc[mt][nt][0] + bx);
            float t1 = gelu_exact(acc[mt][nt][1] + by);
            float t2 = gelu_exact(acc[mt][nt][2] + bx);
            float t3 = gelu_exact(acc[mt][nt][3] + by);
            uint32_t hA = pack_bf16x2(t1, t0);
            uint32_t hB = pack_bf16x2(t3, t2);
            float hA0 = __uint_as_float(hA << 16);
            float hA1 = __uint_as_float(hA & 0xffff0000u);
            float hB0 = __uint_as_float(hB << 16);
            float hB1 = __uint_as_float(hB & 0xffff0000u);
            uint32_t lA = pack_bf16x2(t1 - hA1, t0 - hA0);
            uint32_t lB = pack_bf16x2(t3 - hB1, t2 - hB0);
            *(uint32_t*)&Ahi[r1 * KST + col] = hA;
            *(uint32_t*)&Alo[r1 * KST + col] = lA;
            *(uint32_t*)&Ahi[r2 * KST + col] = hB;
            *(uint32_t*)&Alo[r2 * KST + col] = lB;
        }
    }
    asm volatile("cp.async.wait_group 0;" ::: "memory");
    __syncthreads();

#pragma unroll
    for (int mt = 0; mt < 2; mt++)
#pragma unroll
        for (int nt = 0; nt < 6; nt++)
#pragma unroll
            for (int q = 0; q < 4; q++) acc[mt][nt][q] = 0.f;

    mma_pass(sbase, fo, acc);      // V = t @ W2

#pragma unroll
    for (int mt = 0; mt < 2; mt++) {
#pragma unroll
        for (int nt = 0; nt < 6; nt++) {
            int col = n0 + nt * 8 + lk;
            float bx = B2s[col], by = B2s[col + 1];
            int r1 = row0 + m0 + mt * 16 + lr;
            int r2 = r1 + 8;
            if (r1 < N_NODES) {
                size_t o = (size_t)r1 * HID + col;
                float2 xv = *(const float2*)(g_aggr + o);
                *(float2*)(out + o) = make_float2(xv.x + gelu_exact(acc[mt][nt][0] + bx),
                                                  xv.y + gelu_exact(acc[mt][nt][1] + by));
            }
            if (r2 < N_NODES) {
                size_t o = (size_t)r2 * HID + col;
                float2 xv = *(const float2*)(g_aggr + o);
                *(float2*)(out + o) = make_float2(xv.x + gelu_exact(acc[mt][nt][2] + bx),
                                                  xv.y + gelu_exact(acc[mt][nt][3] + by));
            }
        }
    }
}

// Edge scatter: aggr[dst] += h[src] * bases, one float4 per thread (fully coalesced).
__global__ __launch_bounds__(256)
void edge_kernel(const float* __restrict__ bases,
                 const int* __restrict__ src,
                 const int* __restrict__ dst) {
    int idx = blockIdx.x * 256 + threadIdx.x;
    if (idx >= N_EDGES * 24) return;
    int e = idx / 24;
    int c = idx - e * 24;
    int s = src[e];
    int d = dst[e];
    float4 b  = ((const float4*)bases)[idx];
    float4 hv = ((const float4*)(g_h + (size_t)s * HID))[c];
    float4 m  = make_float4(b.x * hv.x, b.y * hv.y, b.z * hv.z, b.w * hv.w);
    float* p = g_aggr + (size_t)d * HID + c * 4;
    asm volatile("red.global.add.v4.f32 [%0], {%1, %2, %3, %4};"
                 :: "l"(p), "f"(m.x), "f"(m.y), "f"(m.z), "f"(m.w)
                 : "memory");
}

extern "C" void kernel_launch(void* const* d_in, const int* in_sizes, int n_in,
                              void* d_out, int out_size) {
    const float* x_feat = (const float*)d_in[0];
    const float* bases  = (const float*)d_in[1];
    const float* W_pre  = (const float*)d_in[2];
    const float* b_pre  = (const float*)d_in[3];
    const float* W1     = (const float*)d_in[4];
    const float* b1     = (const float*)d_in[5];
    const float* W2     = (const float*)d_in[6];
    const float* b2     = (const float*)d_in[7];
    const int*   src    = (const int*)d_in[8];
    const int*   dst    = (const int*)d_in[9];
    float* out = (float*)d_out;

    cudaFuncSetAttribute(gemm_pre, cudaFuncAttributeMaxDynamicSharedMemorySize, SM_TOT);
    cudaFuncSetAttribute(gemm_ffn, cudaFuncAttributeMaxDynamicSharedMemorySize, SM_TOT);

    float* g_h_p;    cudaGetSymbolAddress((void**)&g_h_p, g_h);
    unsigned char* wcvt_p; cudaGetSymbolAddress((void**)&wcvt_p, g_wcvt);

    const int gemm_grid = (N_NODES + BM - 1) / BM;   // 391
    const int edge_grid = (N_EDGES * 24 + 255) / 256;

    wconv_kernel<<<96, 256>>>(W_pre, W1, W2);
    // 1) h = gelu(x_feat @ W_pre + b_pre); g_aggr = x_feat
    gemm_pre<<<gemm_grid, 256, SM_TOT>>>(x_feat, wcvt_p, b_pre, g_h_p);
    // 2) g_aggr[dst] += h[src] * bases   (g_aggr becomes x)
    edge_kernel<<<edge_grid, 256>>>(bases, src, dst);
    // 3+4) t = gelu(x@W1+b1); out = x + gelu(t@W2+b2)
    gemm_ffn<<<gemm_grid, 256, SM_TOT>>>(wcvt_p + WMAT_BYTES, wcvt_p + 2 * WMAT_BYTES,
                                         b1, b2, out);
}